// round 16
// baseline (speedup 1.0000x reference)
#include <cuda_runtime.h>
#include <cuda_fp16.h>
#include <cstdint>
#include <math.h>

#define NROWS 8192
#define CDIM  256

#define BM 128
#define BN 128
#define BK 32
#define NKT (CDIM / BK)          // 8 k-tiles
#define NCOLB (NROWS / BN)       // 64
#define NROWB (NROWS / BM)       // 64
#define NSTRICT (NCOLB * (NCOLB - 1) / 2)  // 2016 strict upper tiles
#define NTILES  (NSTRICT + NCOLB)          // + 64 diagonal tiles = 2080

// Fragment-order fp16 operand layouts (m16n8k16 fragments), as in R7.
__device__ __align__(1024) __half g_fnA[NROWS * CDIM];
__device__ __align__(1024) __half g_fnB[NROWS * CDIM];
__device__ float g_denp[NCOLB * NROWS];
__device__ float g_posp[NCOLB * NROWS];
__device__ float g_cntp[NCOLB * NROWS];
__device__ float g_rowval[NROWS];
__device__ float g_losspart[32];

__device__ __forceinline__ uint32_t smem_u32(const void* p) {
    uint32_t a;
    asm("{ .reg .u64 t; cvta.to.shared.u64 t, %1; cvt.u32.u64 %0, t; }" : "=r"(a) : "l"(p));
    return a;
}
__device__ __forceinline__ void cp_async16(uint32_t s, const void* g) {
    asm volatile("cp.async.ca.shared.global [%0], [%1], 16;" :: "r"(s), "l"(g));
}
#define CP_COMMIT() asm volatile("cp.async.commit_group;" ::: "memory")
#define CP_WAIT(n)  asm volatile("cp.async.wait_group %0;" :: "n"(n) : "memory")

__device__ __forceinline__ void mma_f16(float c[4], const uint32_t a[4], const uint32_t b[2]) {
    asm volatile(
        "mma.sync.aligned.m16n8k16.row.col.f32.f16.f16.f32 "
        "{%0,%1,%2,%3}, {%4,%5,%6,%7}, {%8,%9}, {%0,%1,%2,%3};"
        : "+f"(c[0]), "+f"(c[1]), "+f"(c[2]), "+f"(c[3])
        : "r"(a[0]), "r"(a[1]), "r"(a[2]), "r"(a[3]), "r"(b[0]), "r"(b[1]));
}

// ---------------------------------------------------------------------------
// K0: L2-normalize 16 rows per block; coalesced fragment-layout emission.
// ---------------------------------------------------------------------------
__global__ __launch_bounds__(256)
void normalize_kernel(const float* __restrict__ f) {
    __shared__ __half sh[16][256];
    const int R   = blockIdx.x;
    const int tid = threadIdx.x;
    const int rloc = tid >> 4;
    const int seg  = tid & 15;

    const float* rowp = f + (size_t)(R * 16 + rloc) * CDIM + seg * 16;
    float vals[16];
    float ss = 0.f;
    #pragma unroll
    for (int i = 0; i < 4; i++) {
        float4 v = *(const float4*)(rowp + i * 4);
        vals[i*4+0] = v.x; vals[i*4+1] = v.y; vals[i*4+2] = v.z; vals[i*4+3] = v.w;
        ss += v.x * v.x + v.y * v.y + v.z * v.z + v.w * v.w;
    }
    #pragma unroll
    for (int o = 1; o <= 8; o <<= 1) ss += __shfl_xor_sync(0xffffffffu, ss, o);
    const float scale = 1.0f / fmaxf(sqrtf(ss), 1e-8f);
    #pragma unroll
    for (int i = 0; i < 16; i++)
        sh[rloc][seg * 16 + i] = __float2half_rn(vals[i] * scale);
    __syncthreads();

    uint32_t* gA = (uint32_t*)g_fnA;
    #pragma unroll
    for (int i = 0; i < 8; i++) {
        int idx = tid + i * 256;
        int K16 = idx >> 7, u = idx & 127;
        int L = u >> 2, s4 = u & 3;
        int g = L >> 2, tt = L & 3, hi = s4 >> 1, wh = s4 & 1;
        int row_local = wh * 8 + g;
        int k = K16 * 16 + hi * 8 + tt * 2;
        gA[(size_t)(R * 16 + K16) * 128 + u] = *(const uint32_t*)&sh[row_local][k];
    }
    uint32_t* gB = (uint32_t*)g_fnB;
    #pragma unroll
    for (int i = 0; i < 8; i++) {
        int idx = tid + i * 256;
        int b = idx >> 6, u = idx & 63;
        int n8 = b >> 4, K16 = b & 15;
        int g = u >> 3, tt = (u >> 1) & 3, hi = u & 1;
        int row_local = n8 * 8 + g;
        int k = K16 * 16 + hi * 8 + tt * 2;
        gB[(size_t)((R * 2 + n8) * 16 + K16) * 64 + u] = *(const uint32_t*)&sh[row_local][k];
    }
}

// ---------------------------------------------------------------------------
// K1: symmetric fp16 GEMM, 1D grid ordered LONGEST-FIRST: strict upper tiles
// (kk < 2016) then diagonal tiles (kk >= 2016) so the drain tail is short.
// Mainloop/epilogue identical to R13 (best verified).
// ---------------------------------------------------------------------------
__global__ __launch_bounds__(256, 2)
void gemm_tc(const int* __restrict__ labels,
             float* __restrict__ out_logits,
             float* __restrict__ out_perfect) {
    int I, J;
    int kk = blockIdx.x;
    if (kk < NSTRICT) {
        // strict upper triangle: S(I) = 63I - I(I-1)/2 tiles precede row I
        I = (int)((127.0f - sqrtf(fmaxf(127.0f * 127.0f - 8.0f * (float)kk, 0.0f))) * 0.5f);
        while (63 * I - (I * (I - 1)) / 2 > kk) I--;
        while (63 * (I + 1) - ((I + 1) * I) / 2 <= kk) I++;
        J = I + 1 + (kk - (63 * I - (I * (I - 1)) / 2));
    } else {
        I = J = kk - NSTRICT;    // diagonal tiles issued last (shortest work)
    }
    const bool isDiag = (I == J);

    __shared__ float sbuf[8448];
    __shared__ __align__(16) int labR[BM];
    __shared__ __align__(16) int labC[BN];
    __shared__ float sred[4][3][BM];
    __shared__ float sredC[2][3][BN];

    const int tid  = threadIdx.x;
    const int lane = tid & 31;
    const int wid  = tid >> 5;
    const int warp_m = wid & 1;
    const int warp_n = wid >> 1;
    const int rowBase = I * BM;
    const int colBase = J * BN;
    const int g = lane >> 2, t = lane & 3;

    if (tid < 128) labR[tid] = labels[rowBase + tid];
    else           labC[tid - 128] = labels[colBase + tid - 128];

    float c[4][4][4];
    #pragma unroll
    for (int mi = 0; mi < 4; mi++)
        #pragma unroll
        for (int ni = 0; ni < 4; ni++)
            #pragma unroll
            for (int q = 0; q < 4; q++) c[mi][ni][q] = 0.0f;

    const int rB16 = rowBase >> 4;
    const int cB8  = colBase >> 3;

    auto fill = [&](int s, int kt) {
        uint32_t sAu = smem_u32(&sbuf[s * 2048]);
        uint32_t sBu = smem_u32(&sbuf[4096 + s * 2048]);
        #pragma unroll
        for (int i = 0; i < 2; i++) {
            int ca = tid + i * 256;
            int blk = ca >> 5, w = ca & 31;
            int gblk = (rB16 + (blk >> 1)) * 16 + kt * 2 + (blk & 1);
            cp_async16(sAu + blk * 512 + w * 16,
                       (const char*)g_fnA + (size_t)gblk * 512 + w * 16);
            int bblk = ca >> 4, bw = ca & 15;
            int gbb = (cB8 + (bblk >> 1)) * 16 + kt * 2 + (bblk & 1);
            cp_async16(sBu + bblk * 256 + bw * 16,
                       (const char*)g_fnB + (size_t)gbb * 256 + bw * 16);
        }
    };

    auto load_frags = [&](int s, int ks, uint32_t a[4][4], uint32_t b[4][2]) {
        #pragma unroll
        for (int mi = 0; mi < 4; mi++) {
            const float4 va = *(const float4*)&sbuf[s * 2048 + ((warp_m * 4 + mi) * 2 + ks) * 128 + lane * 4];
            a[mi][0] = __float_as_uint(va.x); a[mi][1] = __float_as_uint(va.y);
            a[mi][2] = __float_as_uint(va.z); a[mi][3] = __float_as_uint(va.w);
        }
        #pragma unroll
        for (int ni = 0; ni < 4; ni++) {
            const float2 vb = *(const float2*)&sbuf[4096 + s * 2048 + ((warp_n * 4 + ni) * 2 + ks) * 64 + lane * 2];
            b[ni][0] = __float_as_uint(vb.x); b[ni][1] = __float_as_uint(vb.y);
        }
    };

    fill(0, 0); CP_COMMIT();
    fill(1, 1); CP_COMMIT();

    #pragma unroll 1
    for (int kt = 0; kt < NKT; kt++) {
        if (kt < NKT - 1) { CP_WAIT(1); } else { CP_WAIT(0); }
        __syncthreads();
        const int s = kt & 1;
        {
            uint32_t a0[4][4], b0[4][2];
            load_frags(s, 0, a0, b0);
            #pragma unroll
            for (int mi = 0; mi < 4; mi++)
                #pragma unroll
                for (int ni = 0; ni < 4; ni++)
                    mma_f16(c[mi][ni], a0[mi], b0[ni]);
        }
        {
            uint32_t a1[4][4], b1[4][2];
            load_frags(s, 1, a1, b1);
            __syncthreads();
            if (kt + 2 < NKT) { fill(s, kt + 2); CP_COMMIT(); }
            #pragma unroll
            for (int mi = 0; mi < 4; mi++)
                #pragma unroll
                for (int ni = 0; ni < 4; ni++)
                    mma_f16(c[mi][ni], a1[mi], b1[ni]);
        }
    }

    // ---------------- Fused epilogue ----------------
    #pragma unroll
    for (int mi = 0; mi < 4; mi++)
        #pragma unroll
        for (int ni = 0; ni < 4; ni++)
            #pragma unroll
            for (int q = 0; q < 4; q++) c[mi][ni][q] *= 10.0f;

    float cD[4][2], cP[4][2], cC[4][2];
    #pragma unroll
    for (int ni = 0; ni < 4; ni++)
        #pragma unroll
        for (int q = 0; q < 2; q++) { cD[ni][q] = 0.f; cP[ni][q] = 0.f; cC[ni][q] = 0.f; }

    if (!isDiag) {
        #pragma unroll
        for (int mi = 0; mi < 4; mi++) {
            const int r0l = warp_m * 64 + mi * 16 + g;
            const int r1l = r0l + 8;
            const int lab0 = labR[r0l], lab1 = labR[r1l];
            float d0 = 0.f, p0 = 0.f, n0 = 0.f, d1 = 0.f, p1 = 0.f, n1 = 0.f;
            #pragma unroll
            for (int ni = 0; ni < 4; ni++) {
                const int cl = warp_n * 32 + ni * 8 + 2 * t;
                const float v00 = c[mi][ni][0], v01 = c[mi][ni][1];
                const float v10 = c[mi][ni][2], v11 = c[mi][ni][3];
                const int lc0 = labC[cl], lc1 = labC[cl + 1];
                const float e00 = __expf(v00), e01 = __expf(v01);
                const float e10 = __expf(v10), e11 = __expf(v11);
                d0 += e00; if (lc0 == lab0) { p0 += v00; n0 += 1.f; }
                d0 += e01; if (lc1 == lab0) { p0 += v01; n0 += 1.f; }
                d1 += e10; if (lc0 == lab1) { p1 += v10; n1 += 1.f; }
                d1 += e11; if (lc1 == lab1) { p1 += v11; n1 += 1.f; }
                cD[ni][0] += e00 + e10;
                cD[ni][1] += e01 + e11;
                if (lc0 == lab0) { cP[ni][0] += v00; cC[ni][0] += 1.f; }
                if (lc0 == lab1) { cP[ni][0] += v10; cC[ni][0] += 1.f; }
                if (lc1 == lab0) { cP[ni][1] += v01; cC[ni][1] += 1.f; }
                if (lc1 == lab1) { cP[ni][1] += v11; cC[ni][1] += 1.f; }
            }
            #pragma unroll
            for (int o = 1; o <= 2; o <<= 1) {
                d0 += __shfl_xor_sync(0xffffffffu, d0, o);
                p0 += __shfl_xor_sync(0xffffffffu, p0, o);
                n0 += __shfl_xor_sync(0xffffffffu, n0, o);
                d1 += __shfl_xor_sync(0xffffffffu, d1, o);
                p1 += __shfl_xor_sync(0xffffffffu, p1, o);
                n1 += __shfl_xor_sync(0xffffffffu, n1, o);
            }
            if (t == 0) {
                sred[warp_n][0][r0l] = d0; sred[warp_n][1][r0l] = p0; sred[warp_n][2][r0l] = n0;
                sred[warp_n][0][r1l] = d1; sred[warp_n][1][r1l] = p1; sred[warp_n][2][r1l] = n1;
            }
        }
        #pragma unroll
        for (int ni = 0; ni < 4; ni++)
            #pragma unroll
            for (int q = 0; q < 2; q++) {
                #pragma unroll
                for (int o = 4; o <= 16; o <<= 1) {
                    cD[ni][q] += __shfl_xor_sync(0xffffffffu, cD[ni][q], o);
                    cP[ni][q] += __shfl_xor_sync(0xffffffffu, cP[ni][q], o);
                    cC[ni][q] += __shfl_xor_sync(0xffffffffu, cC[ni][q], o);
                }
            }
        if (lane < 4) {
            #pragma unroll
            for (int ni = 0; ni < 4; ni++) {
                int cl = warp_n * 32 + ni * 8 + 2 * t;
                sredC[warp_m][0][cl]     = cD[ni][0];
                sredC[warp_m][1][cl]     = cP[ni][0];
                sredC[warp_m][2][cl]     = cC[ni][0];
                sredC[warp_m][0][cl + 1] = cD[ni][1];
                sredC[warp_m][1][cl + 1] = cP[ni][1];
                sredC[warp_m][2][cl + 1] = cC[ni][1];
            }
        }
    } else {
        #pragma unroll
        for (int mi = 0; mi < 4; mi++) {
            const int r0l = warp_m * 64 + mi * 16 + g;
            const int r1l = r0l + 8;
            const int gr0 = rowBase + r0l, gr1 = rowBase + r1l;
            const int lab0 = labR[r0l], lab1 = labR[r1l];
            float d0 = 0.f, p0 = 0.f, n0 = 0.f, d1 = 0.f, p1 = 0.f, n1 = 0.f;
            #pragma unroll
            for (int ni = 0; ni < 4; ni++) {
                const int cl = warp_n * 32 + ni * 8 + 2 * t;
                const int gc = colBase + cl;
                const float v00 = c[mi][ni][0], v01 = c[mi][ni][1];
                const float v10 = c[mi][ni][2], v11 = c[mi][ni][3];
                const int lc0 = labC[cl], lc1 = labC[cl + 1];
                const float e00 = __expf(v00), e01 = __expf(v01);
                const float e10 = __expf(v10), e11 = __expf(v11);
                if (gc != gr0)     { d0 += e00; if (lc0 == lab0) { p0 += v00; n0 += 1.f; } }
                if (gc + 1 != gr0) { d0 += e01; if (lc1 == lab0) { p0 += v01; n0 += 1.f; } }
                if (gc != gr1)     { d1 += e10; if (lc0 == lab1) { p1 += v10; n1 += 1.f; } }
                if (gc + 1 != gr1) { d1 += e11; if (lc1 == lab1) { p1 += v11; n1 += 1.f; } }
            }
            #pragma unroll
            for (int o = 1; o <= 2; o <<= 1) {
                d0 += __shfl_xor_sync(0xffffffffu, d0, o);
                p0 += __shfl_xor_sync(0xffffffffu, p0, o);
                n0 += __shfl_xor_sync(0xffffffffu, n0, o);
                d1 += __shfl_xor_sync(0xffffffffu, d1, o);
                p1 += __shfl_xor_sync(0xffffffffu, p1, o);
                n1 += __shfl_xor_sync(0xffffffffu, n1, o);
            }
            if (t == 0) {
                sred[warp_n][0][r0l] = d0; sred[warp_n][1][r0l] = p0; sred[warp_n][2][r0l] = n0;
                sred[warp_n][0][r1l] = d1; sred[warp_n][1][r1l] = p1; sred[warp_n][2][r1l] = n1;
            }
        }
    }
    __syncthreads();

    if (tid < BM) {
        float D = 0.f, P = 0.f, C = 0.f;
        #pragma unroll
        for (int wn = 0; wn < 4; wn++) {
            D += sred[wn][0][tid]; P += sred[wn][1][tid]; C += sred[wn][2][tid];
        }
        const size_t slot = (size_t)J * NROWS + rowBase + tid;
        g_denp[slot] = D; g_posp[slot] = P; g_cntp[slot] = C;
    } else if (!isDiag) {
        const int jc = tid - 128;
        const float D = sredC[0][0][jc] + sredC[1][0][jc];
        const float P = sredC[0][1][jc] + sredC[1][1][jc];
        const float C = sredC[0][2][jc] + sredC[1][2][jc];
        const size_t slot = (size_t)I * NROWS + colBase + jc;
        g_denp[slot] = D; g_posp[slot] = P; g_cntp[slot] = C;
    }

    // ---- Direct logits tile: stage (stride 132), vectorized stores ----
    #pragma unroll 1
    for (int h = 0; h < 2; h++) {
        __syncthreads();
        if (warp_m == h) {
            #pragma unroll
            for (int mi = 0; mi < 4; mi++)
                #pragma unroll
                for (int ni = 0; ni < 4; ni++)
                    #pragma unroll
                    for (int q = 0; q < 4; q++) {
                        int rl = mi * 16 + g + 8 * (q >> 1);
                        int cl = warp_n * 32 + ni * 8 + 2 * t + (q & 1);
                        sbuf[rl * 132 + cl] = c[mi][ni][q];
                    }
        }
        __syncthreads();
        #pragma unroll
        for (int i = 0; i < 8; i++) {
            int rr = wid + i * 8;
            float4 v = *(const float4*)&sbuf[rr * 132 + lane * 4];
            float wprev = __shfl_up_sync(0xffffffffu, v.w, 1);
            if (lane > 0) {
                float4 o = make_float4(wprev, v.x, v.y, v.z);
                *(float4*)&out_logits[(size_t)(rowBase + h * 64 + rr) * NROWS + colBase + 4 * lane - 1] = o;
            }
        }
        {
            int rr = tid >> 2, e = tid & 3;
            int cc = (e == 3) ? 127 : e;
            out_logits[(size_t)(rowBase + h * 64 + rr) * NROWS + colBase + cc] = sbuf[rr * 132 + cc];
        }
    }

    // ---- Mirror logits tile (transposed staging, stride 132), vectorized ----
    if (!isDiag) {
        #pragma unroll 1
        for (int p = 0; p < 2; p++) {
            __syncthreads();
            if ((warp_n >> 1) == p) {
                #pragma unroll
                for (int mi = 0; mi < 4; mi++)
                    #pragma unroll
                    for (int ni = 0; ni < 4; ni++)
                        #pragma unroll
                        for (int q = 0; q < 4; q++) {
                            int cl = (warp_n & 1) * 32 + ni * 8 + 2 * t + (q & 1);
                            int rl = warp_m * 64 + mi * 16 + g + 8 * (q >> 1);
                            sbuf[cl * 132 + rl] = c[mi][ni][q];
                        }
            }
            __syncthreads();
            #pragma unroll
            for (int i = 0; i < 8; i++) {
                int rr = wid + i * 8;
                float4 v = *(const float4*)&sbuf[rr * 132 + lane * 4];
                float wprev = __shfl_up_sync(0xffffffffu, v.w, 1);
                if (lane > 0) {
                    float4 o = make_float4(wprev, v.x, v.y, v.z);
                    *(float4*)&out_logits[(size_t)(colBase + p * 64 + rr) * NROWS + rowBase + 4 * lane - 1] = o;
                }
            }
            {
                int rr = tid >> 2, e = tid & 3;
                int cc = (e == 3) ? 127 : e;
                out_logits[(size_t)(colBase + p * 64 + rr) * NROWS + rowBase + cc] = sbuf[rr * 132 + cc];
            }
        }
    }

    // ---- perfect_logit tiles: vectorized from labels ----
    {
        int4 lc4 = *(const int4*)&labC[4 * lane];
        int lcm1 = __shfl_up_sync(0xffffffffu, lc4.w, 1);
        #pragma unroll
        for (int i = 0; i < 16; i++) {
            int rr = wid + i * 8;
            int lr = labR[rr];
            if (lane > 0) {
                float4 o;
                o.x = (lcm1  == lr) ? 1.f : -1.f;
                o.y = (lc4.x == lr) ? 1.f : -1.f;
                o.z = (lc4.y == lr) ? 1.f : -1.f;
                o.w = (lc4.z == lr) ? 1.f : -1.f;
                *(float4*)&out_perfect[(size_t)(rowBase + rr) * NROWS + colBase + 4 * lane - 1] = o;
            }
        }
        #pragma unroll
        for (int i = 0; i < 2; i++) {
            int idx = tid + i * 256;
            int rr = idx >> 2, e = idx & 3;
            int cc = (e == 3) ? 127 : e;
            out_perfect[(size_t)(rowBase + rr) * NROWS + colBase + cc] =
                (labR[rr] == labC[cc]) ? 1.f : -1.f;
        }
    }
    if (!isDiag) {
        int4 lr4 = *(const int4*)&labR[4 * lane];
        int lrm1 = __shfl_up_sync(0xffffffffu, lr4.w, 1);
        #pragma unroll
        for (int i = 0; i < 16; i++) {
            int rr = wid + i * 8;
            int lc_ = labC[rr];
            if (lane > 0) {
                float4 o;
                o.x = (lrm1  == lc_) ? 1.f : -1.f;
                o.y = (lr4.x == lc_) ? 1.f : -1.f;
                o.z = (lr4.y == lc_) ? 1.f : -1.f;
                o.w = (lr4.z == lc_) ? 1.f : -1.f;
                *(float4*)&out_perfect[(size_t)(colBase + rr) * NROWS + rowBase + 4 * lane - 1] = o;
            }
        }
        #pragma unroll
        for (int i = 0; i < 2; i++) {
            int idx = tid + i * 256;
            int rr = idx >> 2, e = idx & 3;
            int cc = (e == 3) ? 127 : e;
            out_perfect[(size_t)(colBase + rr) * NROWS + rowBase + cc] =
                (labC[rr] == labR[cc]) ? 1.f : -1.f;
        }
    }
}

// ---------------------------------------------------------------------------
// K2: reduce partials -> per-row value; block-reduce loss partials.
// ---------------------------------------------------------------------------
__global__ void rowfinal_kernel() {
    const int tid = threadIdx.x;
    int i = blockIdx.x * 256 + tid;
    float D = 0.f, P = 0.f, C = 0.f;
    #pragma unroll 4
    for (int b = 0; b < NCOLB; b++) {
        D += g_denp[(size_t)b * NROWS + i];
        P += g_posp[(size_t)b * NROWS + i];
        C += g_cntp[(size_t)b * NROWS + i];
    }
    float rv = -(P - C * logf(D)) / (C + 1e-6f);
    g_rowval[i] = rv;

    __shared__ float rd[8];
    float s = rv;
    #pragma unroll
    for (int o = 16; o > 0; o >>= 1) s += __shfl_xor_sync(0xffffffffu, s, o);
    if ((tid & 31) == 0) rd[tid >> 5] = s;
    __syncthreads();
    if (tid == 0) {
        float tot = 0.f;
        #pragma unroll
        for (int w = 0; w < 8; w++) tot += rd[w];
        g_losspart[blockIdx.x] = tot;
    }
}

// ---------------------------------------------------------------------------
// K3: loss = sum(g_losspart) / NROWS  (one warp)
// ---------------------------------------------------------------------------
__global__ void loss_kernel(float* __restrict__ out) {
    const int tid = threadIdx.x;                 // 32
    float s = g_losspart[tid];
    #pragma unroll
    for (int o = 16; o > 0; o >>= 1) s += __shfl_xor_sync(0xffffffffu, s, o);
    if (tid == 0) out[0] = s / (float)NROWS;
}

// ---------------------------------------------------------------------------
// Launch: out = [loss(1) | logits(8192^2) | perfect_logit(8192^2)]
// ---------------------------------------------------------------------------
extern "C" void kernel_launch(void* const* d_in, const int* in_sizes, int n_in,
                              void* d_out, int out_size) {
    const float* features = (const float*)d_in[0];
    const int*   labels   = (const int*)d_in[1];
    float* out         = (float*)d_out;
    float* out_logits  = out + 1;
    float* out_perfect = out + 1 + (size_t)NROWS * NROWS;

    normalize_kernel<<<NROWS / 16, 256>>>(features);
    gemm_tc<<<NTILES, 256>>>(labels, out_logits, out_perfect);   // off-diag first, diag last
    rowfinal_kernel<<<NROWS / 256, 256>>>();                     // 32 blocks
    loss_kernel<<<1, 32>>>(out);
}

// round 17
// speedup vs baseline: 1.0923x; 1.0923x over previous
#include <cuda_runtime.h>
#include <cuda_fp16.h>
#include <cstdint>
#include <math.h>

#define NROWS 8192
#define CDIM  256

#define BM 128
#define BN 128
#define BK 32
#define NKT (CDIM / BK)          // 8 k-tiles
#define NCOLB (NROWS / BN)       // 64
#define NROWB (NROWS / BM)       // 64
#define NTILES (NCOLB * (NCOLB + 1) / 2)   // 2080 upper-triangular CTA tiles

// Fragment-order fp16 operand layouts (m16n8k16 fragments), as in R7.
__device__ __align__(1024) __half g_fnA[NROWS * CDIM];
__device__ __align__(1024) __half g_fnB[NROWS * CDIM];
__device__ float g_denp[NCOLB * NROWS];
__device__ float g_posp[NCOLB * NROWS];
__device__ float g_cntp[NCOLB * NROWS];
__device__ float g_rowval[NROWS];
__device__ float g_losspart[32];

__device__ __forceinline__ uint32_t smem_u32(const void* p) {
    uint32_t a;
    asm("{ .reg .u64 t; cvta.to.shared.u64 t, %1; cvt.u32.u64 %0, t; }" : "=r"(a) : "l"(p));
    return a;
}
__device__ __forceinline__ void cp_async16(uint32_t s, const void* g) {
    asm volatile("cp.async.ca.shared.global [%0], [%1], 16;" :: "r"(s), "l"(g));
}
#define CP_COMMIT() asm volatile("cp.async.commit_group;" ::: "memory")
#define CP_WAIT(n)  asm volatile("cp.async.wait_group %0;" :: "n"(n) : "memory")

// Streaming (evict-first) stores for write-once outputs.
__device__ __forceinline__ void stg_cs_f4(float* p, float4 v) {
    asm volatile("st.global.cs.v4.f32 [%0], {%1,%2,%3,%4};"
                 :: "l"(p), "f"(v.x), "f"(v.y), "f"(v.z), "f"(v.w) : "memory");
}
__device__ __forceinline__ void stg_cs_f(float* p, float v) {
    asm volatile("st.global.cs.f32 [%0], %1;" :: "l"(p), "f"(v) : "memory");
}

__device__ __forceinline__ void mma_f16(float c[4], const uint32_t a[4], const uint32_t b[2]) {
    asm volatile(
        "mma.sync.aligned.m16n8k16.row.col.f32.f16.f16.f32 "
        "{%0,%1,%2,%3}, {%4,%5,%6,%7}, {%8,%9}, {%0,%1,%2,%3};"
        : "+f"(c[0]), "+f"(c[1]), "+f"(c[2]), "+f"(c[3])
        : "r"(a[0]), "r"(a[1]), "r"(a[2]), "r"(a[3]), "r"(b[0]), "r"(b[1]));
}

// ---------------------------------------------------------------------------
// K0: L2-normalize 16 rows per block; coalesced fragment-layout emission.
// ---------------------------------------------------------------------------
__global__ __launch_bounds__(256)
void normalize_kernel(const float* __restrict__ f) {
    __shared__ __half sh[16][256];
    const int R   = blockIdx.x;
    const int tid = threadIdx.x;
    const int rloc = tid >> 4;
    const int seg  = tid & 15;

    const float* rowp = f + (size_t)(R * 16 + rloc) * CDIM + seg * 16;
    float vals[16];
    float ss = 0.f;
    #pragma unroll
    for (int i = 0; i < 4; i++) {
        float4 v = *(const float4*)(rowp + i * 4);
        vals[i*4+0] = v.x; vals[i*4+1] = v.y; vals[i*4+2] = v.z; vals[i*4+3] = v.w;
        ss += v.x * v.x + v.y * v.y + v.z * v.z + v.w * v.w;
    }
    #pragma unroll
    for (int o = 1; o <= 8; o <<= 1) ss += __shfl_xor_sync(0xffffffffu, ss, o);
    const float scale = 1.0f / fmaxf(sqrtf(ss), 1e-8f);
    #pragma unroll
    for (int i = 0; i < 16; i++)
        sh[rloc][seg * 16 + i] = __float2half_rn(vals[i] * scale);
    __syncthreads();

    uint32_t* gA = (uint32_t*)g_fnA;
    #pragma unroll
    for (int i = 0; i < 8; i++) {
        int idx = tid + i * 256;
        int K16 = idx >> 7, u = idx & 127;
        int L = u >> 2, s4 = u & 3;
        int g = L >> 2, tt = L & 3, hi = s4 >> 1, wh = s4 & 1;
        int row_local = wh * 8 + g;
        int k = K16 * 16 + hi * 8 + tt * 2;
        gA[(size_t)(R * 16 + K16) * 128 + u] = *(const uint32_t*)&sh[row_local][k];
    }
    uint32_t* gB = (uint32_t*)g_fnB;
    #pragma unroll
    for (int i = 0; i < 8; i++) {
        int idx = tid + i * 256;
        int b = idx >> 6, u = idx & 63;
        int n8 = b >> 4, K16 = b & 15;
        int g = u >> 3, tt = (u >> 1) & 3, hi = u & 1;
        int row_local = n8 * 8 + g;
        int k = K16 * 16 + hi * 8 + tt * 2;
        gB[(size_t)((R * 2 + n8) * 16 + K16) * 64 + u] = *(const uint32_t*)&sh[row_local][k];
    }
}

// ---------------------------------------------------------------------------
// K1: symmetric fp16 GEMM (R13 structure, verified 166.0); all output stores
// use st.global.cs (write-once data, keep operands L2-resident).
// ---------------------------------------------------------------------------
__global__ __launch_bounds__(256, 2)
void gemm_tc(const int* __restrict__ labels,
             float* __restrict__ out_logits,
             float* __restrict__ out_perfect) {
    int kk = blockIdx.x;
    int I = (int)((129.0f - sqrtf(fmaxf(129.0f * 129.0f - 8.0f * (float)kk, 0.0f))) * 0.5f);
    while (64 * I - (I * (I - 1)) / 2 > kk) I--;
    while (64 * (I + 1) - ((I + 1) * I) / 2 <= kk) I++;
    const int J = I + (kk - (64 * I - (I * (I - 1)) / 2));
    const bool isDiag = (I == J);

    __shared__ float sbuf[8448];
    __shared__ __align__(16) int labR[BM];
    __shared__ __align__(16) int labC[BN];
    __shared__ float sred[4][3][BM];
    __shared__ float sredC[2][3][BN];

    const int tid  = threadIdx.x;
    const int lane = tid & 31;
    const int wid  = tid >> 5;
    const int warp_m = wid & 1;
    const int warp_n = wid >> 1;
    const int rowBase = I * BM;
    const int colBase = J * BN;
    const int g = lane >> 2, t = lane & 3;

    if (tid < 128) labR[tid] = labels[rowBase + tid];
    else           labC[tid - 128] = labels[colBase + tid - 128];

    float c[4][4][4];
    #pragma unroll
    for (int mi = 0; mi < 4; mi++)
        #pragma unroll
        for (int ni = 0; ni < 4; ni++)
            #pragma unroll
            for (int q = 0; q < 4; q++) c[mi][ni][q] = 0.0f;

    const int rB16 = rowBase >> 4;
    const int cB8  = colBase >> 3;

    auto fill = [&](int s, int kt) {
        uint32_t sAu = smem_u32(&sbuf[s * 2048]);
        uint32_t sBu = smem_u32(&sbuf[4096 + s * 2048]);
        #pragma unroll
        for (int i = 0; i < 2; i++) {
            int ca = tid + i * 256;
            int blk = ca >> 5, w = ca & 31;
            int gblk = (rB16 + (blk >> 1)) * 16 + kt * 2 + (blk & 1);
            cp_async16(sAu + blk * 512 + w * 16,
                       (const char*)g_fnA + (size_t)gblk * 512 + w * 16);
            int bblk = ca >> 4, bw = ca & 15;
            int gbb = (cB8 + (bblk >> 1)) * 16 + kt * 2 + (bblk & 1);
            cp_async16(sBu + bblk * 256 + bw * 16,
                       (const char*)g_fnB + (size_t)gbb * 256 + bw * 16);
        }
    };

    auto load_frags = [&](int s, int ks, uint32_t a[4][4], uint32_t b[4][2]) {
        #pragma unroll
        for (int mi = 0; mi < 4; mi++) {
            const float4 va = *(const float4*)&sbuf[s * 2048 + ((warp_m * 4 + mi) * 2 + ks) * 128 + lane * 4];
            a[mi][0] = __float_as_uint(va.x); a[mi][1] = __float_as_uint(va.y);
            a[mi][2] = __float_as_uint(va.z); a[mi][3] = __float_as_uint(va.w);
        }
        #pragma unroll
        for (int ni = 0; ni < 4; ni++) {
            const float2 vb = *(const float2*)&sbuf[4096 + s * 2048 + ((warp_n * 4 + ni) * 2 + ks) * 64 + lane * 2];
            b[ni][0] = __float_as_uint(vb.x); b[ni][1] = __float_as_uint(vb.y);
        }
    };

    fill(0, 0); CP_COMMIT();
    fill(1, 1); CP_COMMIT();

    #pragma unroll 1
    for (int kt = 0; kt < NKT; kt++) {
        if (kt < NKT - 1) { CP_WAIT(1); } else { CP_WAIT(0); }
        __syncthreads();
        const int s = kt & 1;
        {
            uint32_t a0[4][4], b0[4][2];
            load_frags(s, 0, a0, b0);
            #pragma unroll
            for (int mi = 0; mi < 4; mi++)
                #pragma unroll
                for (int ni = 0; ni < 4; ni++)
                    mma_f16(c[mi][ni], a0[mi], b0[ni]);
        }
        {
            uint32_t a1[4][4], b1[4][2];
            load_frags(s, 1, a1, b1);
            __syncthreads();
            if (kt + 2 < NKT) { fill(s, kt + 2); CP_COMMIT(); }
            #pragma unroll
            for (int mi = 0; mi < 4; mi++)
                #pragma unroll
                for (int ni = 0; ni < 4; ni++)
                    mma_f16(c[mi][ni], a1[mi], b1[ni]);
        }
    }

    // ---------------- Fused epilogue ----------------
    #pragma unroll
    for (int mi = 0; mi < 4; mi++)
        #pragma unroll
        for (int ni = 0; ni < 4; ni++)
            #pragma unroll
            for (int q = 0; q < 4; q++) c[mi][ni][q] *= 10.0f;

    float cD[4][2], cP[4][2], cC[4][2];
    #pragma unroll
    for (int ni = 0; ni < 4; ni++)
        #pragma unroll
        for (int q = 0; q < 2; q++) { cD[ni][q] = 0.f; cP[ni][q] = 0.f; cC[ni][q] = 0.f; }

    if (!isDiag) {
        #pragma unroll
        for (int mi = 0; mi < 4; mi++) {
            const int r0l = warp_m * 64 + mi * 16 + g;
            const int r1l = r0l + 8;
            const int lab0 = labR[r0l], lab1 = labR[r1l];
            float d0 = 0.f, p0 = 0.f, n0 = 0.f, d1 = 0.f, p1 = 0.f, n1 = 0.f;
            #pragma unroll
            for (int ni = 0; ni < 4; ni++) {
                const int cl = warp_n * 32 + ni * 8 + 2 * t;
                const float v00 = c[mi][ni][0], v01 = c[mi][ni][1];
                const float v10 = c[mi][ni][2], v11 = c[mi][ni][3];
                const int lc0 = labC[cl], lc1 = labC[cl + 1];
                const float e00 = __expf(v00), e01 = __expf(v01);
                const float e10 = __expf(v10), e11 = __expf(v11);
                d0 += e00; if (lc0 == lab0) { p0 += v00; n0 += 1.f; }
                d0 += e01; if (lc1 == lab0) { p0 += v01; n0 += 1.f; }
                d1 += e10; if (lc0 == lab1) { p1 += v10; n1 += 1.f; }
                d1 += e11; if (lc1 == lab1) { p1 += v11; n1 += 1.f; }
                cD[ni][0] += e00 + e10;
                cD[ni][1] += e01 + e11;
                if (lc0 == lab0) { cP[ni][0] += v00; cC[ni][0] += 1.f; }
                if (lc0 == lab1) { cP[ni][0] += v10; cC[ni][0] += 1.f; }
                if (lc1 == lab0) { cP[ni][1] += v01; cC[ni][1] += 1.f; }
                if (lc1 == lab1) { cP[ni][1] += v11; cC[ni][1] += 1.f; }
            }
            #pragma unroll
            for (int o = 1; o <= 2; o <<= 1) {
                d0 += __shfl_xor_sync(0xffffffffu, d0, o);
                p0 += __shfl_xor_sync(0xffffffffu, p0, o);
                n0 += __shfl_xor_sync(0xffffffffu, n0, o);
                d1 += __shfl_xor_sync(0xffffffffu, d1, o);
                p1 += __shfl_xor_sync(0xffffffffu, p1, o);
                n1 += __shfl_xor_sync(0xffffffffu, n1, o);
            }
            if (t == 0) {
                sred[warp_n][0][r0l] = d0; sred[warp_n][1][r0l] = p0; sred[warp_n][2][r0l] = n0;
                sred[warp_n][0][r1l] = d1; sred[warp_n][1][r1l] = p1; sred[warp_n][2][r1l] = n1;
            }
        }
        #pragma unroll
        for (int ni = 0; ni < 4; ni++)
            #pragma unroll
            for (int q = 0; q < 2; q++) {
                #pragma unroll
                for (int o = 4; o <= 16; o <<= 1) {
                    cD[ni][q] += __shfl_xor_sync(0xffffffffu, cD[ni][q], o);
                    cP[ni][q] += __shfl_xor_sync(0xffffffffu, cP[ni][q], o);
                    cC[ni][q] += __shfl_xor_sync(0xffffffffu, cC[ni][q], o);
                }
            }
        if (lane < 4) {
            #pragma unroll
            for (int ni = 0; ni < 4; ni++) {
                int cl = warp_n * 32 + ni * 8 + 2 * t;
                sredC[warp_m][0][cl]     = cD[ni][0];
                sredC[warp_m][1][cl]     = cP[ni][0];
                sredC[warp_m][2][cl]     = cC[ni][0];
                sredC[warp_m][0][cl + 1] = cD[ni][1];
                sredC[warp_m][1][cl + 1] = cP[ni][1];
                sredC[warp_m][2][cl + 1] = cC[ni][1];
            }
        }
    } else {
        #pragma unroll
        for (int mi = 0; mi < 4; mi++) {
            const int r0l = warp_m * 64 + mi * 16 + g;
            const int r1l = r0l + 8;
            const int gr0 = rowBase + r0l, gr1 = rowBase + r1l;
            const int lab0 = labR[r0l], lab1 = labR[r1l];
            float d0 = 0.f, p0 = 0.f, n0 = 0.f, d1 = 0.f, p1 = 0.f, n1 = 0.f;
            #pragma unroll
            for (int ni = 0; ni < 4; ni++) {
                const int cl = warp_n * 32 + ni * 8 + 2 * t;
                const int gc = colBase + cl;
                const float v00 = c[mi][ni][0], v01 = c[mi][ni][1];
                const float v10 = c[mi][ni][2], v11 = c[mi][ni][3];
                const int lc0 = labC[cl], lc1 = labC[cl + 1];
                const float e00 = __expf(v00), e01 = __expf(v01);
                const float e10 = __expf(v10), e11 = __expf(v11);
                if (gc != gr0)     { d0 += e00; if (lc0 == lab0) { p0 += v00; n0 += 1.f; } }
                if (gc + 1 != gr0) { d0 += e01; if (lc1 == lab0) { p0 += v01; n0 += 1.f; } }
                if (gc != gr1)     { d1 += e10; if (lc0 == lab1) { p1 += v10; n1 += 1.f; } }
                if (gc + 1 != gr1) { d1 += e11; if (lc1 == lab1) { p1 += v11; n1 += 1.f; } }
            }
            #pragma unroll
            for (int o = 1; o <= 2; o <<= 1) {
                d0 += __shfl_xor_sync(0xffffffffu, d0, o);
                p0 += __shfl_xor_sync(0xffffffffu, p0, o);
                n0 += __shfl_xor_sync(0xffffffffu, n0, o);
                d1 += __shfl_xor_sync(0xffffffffu, d1, o);
                p1 += __shfl_xor_sync(0xffffffffu, p1, o);
                n1 += __shfl_xor_sync(0xffffffffu, n1, o);
            }
            if (t == 0) {
                sred[warp_n][0][r0l] = d0; sred[warp_n][1][r0l] = p0; sred[warp_n][2][r0l] = n0;
                sred[warp_n][0][r1l] = d1; sred[warp_n][1][r1l] = p1; sred[warp_n][2][r1l] = n1;
            }
        }
    }
    __syncthreads();

    if (tid < BM) {
        float D = 0.f, P = 0.f, C = 0.f;
        #pragma unroll
        for (int wn = 0; wn < 4; wn++) {
            D += sred[wn][0][tid]; P += sred[wn][1][tid]; C += sred[wn][2][tid];
        }
        const size_t slot = (size_t)J * NROWS + rowBase + tid;
        g_denp[slot] = D; g_posp[slot] = P; g_cntp[slot] = C;
    } else if (!isDiag) {
        const int jc = tid - 128;
        const float D = sredC[0][0][jc] + sredC[1][0][jc];
        const float P = sredC[0][1][jc] + sredC[1][1][jc];
        const float C = sredC[0][2][jc] + sredC[1][2][jc];
        const size_t slot = (size_t)I * NROWS + colBase + jc;
        g_denp[slot] = D; g_posp[slot] = P; g_cntp[slot] = C;
    }

    // ---- Direct logits tile: stage (stride 132), streaming vectorized stores ----
    #pragma unroll 1
    for (int h = 0; h < 2; h++) {
        __syncthreads();
        if (warp_m == h) {
            #pragma unroll
            for (int mi = 0; mi < 4; mi++)
                #pragma unroll
                for (int ni = 0; ni < 4; ni++)
                    #pragma unroll
                    for (int q = 0; q < 4; q++) {
                        int rl = mi * 16 + g + 8 * (q >> 1);
                        int cl = warp_n * 32 + ni * 8 + 2 * t + (q & 1);
                        sbuf[rl * 132 + cl] = c[mi][ni][q];
                    }
        }
        __syncthreads();
        #pragma unroll
        for (int i = 0; i < 8; i++) {
            int rr = wid + i * 8;
            float4 v = *(const float4*)&sbuf[rr * 132 + lane * 4];
            float wprev = __shfl_up_sync(0xffffffffu, v.w, 1);
            if (lane > 0) {
                float4 o = make_float4(wprev, v.x, v.y, v.z);
                stg_cs_f4(&out_logits[(size_t)(rowBase + h * 64 + rr) * NROWS + colBase + 4 * lane - 1], o);
            }
        }
        {
            int rr = tid >> 2, e = tid & 3;
            int cc = (e == 3) ? 127 : e;
            stg_cs_f(&out_logits[(size_t)(rowBase + h * 64 + rr) * NROWS + colBase + cc], sbuf[rr * 132 + cc]);
        }
    }

    // ---- Mirror logits tile (transposed staging), streaming stores ----
    if (!isDiag) {
        #pragma unroll 1
        for (int p = 0; p < 2; p++) {
            __syncthreads();
            if ((warp_n >> 1) == p) {
                #pragma unroll
                for (int mi = 0; mi < 4; mi++)
                    #pragma unroll
                    for (int ni = 0; ni < 4; ni++)
                        #pragma unroll
                        for (int q = 0; q < 4; q++) {
                            int cl = (warp_n & 1) * 32 + ni * 8 + 2 * t + (q & 1);
                            int rl = warp_m * 64 + mi * 16 + g + 8 * (q >> 1);
                            sbuf[cl * 132 + rl] = c[mi][ni][q];
                        }
            }
            __syncthreads();
            #pragma unroll
            for (int i = 0; i < 8; i++) {
                int rr = wid + i * 8;
                float4 v = *(const float4*)&sbuf[rr * 132 + lane * 4];
                float wprev = __shfl_up_sync(0xffffffffu, v.w, 1);
                if (lane > 0) {
                    float4 o = make_float4(wprev, v.x, v.y, v.z);
                    stg_cs_f4(&out_logits[(size_t)(colBase + p * 64 + rr) * NROWS + rowBase + 4 * lane - 1], o);
                }
            }
            {
                int rr = tid >> 2, e = tid & 3;
                int cc = (e == 3) ? 127 : e;
                stg_cs_f(&out_logits[(size_t)(colBase + p * 64 + rr) * NROWS + rowBase + cc], sbuf[rr * 132 + cc]);
            }
        }
    }

    // ---- perfect_logit tiles: streaming vectorized stores from labels ----
    {
        int4 lc4 = *(const int4*)&labC[4 * lane];
        int lcm1 = __shfl_up_sync(0xffffffffu, lc4.w, 1);
        #pragma unroll
        for (int i = 0; i < 16; i++) {
            int rr = wid + i * 8;
            int lr = labR[rr];
            if (lane > 0) {
                float4 o;
                o.x = (lcm1  == lr) ? 1.f : -1.f;
                o.y = (lc4.x == lr) ? 1.f : -1.f;
                o.z = (lc4.y == lr) ? 1.f : -1.f;
                o.w = (lc4.z == lr) ? 1.f : -1.f;
                stg_cs_f4(&out_perfect[(size_t)(rowBase + rr) * NROWS + colBase + 4 * lane - 1], o);
            }
        }
        #pragma unroll
        for (int i = 0; i < 2; i++) {
            int idx = tid + i * 256;
            int rr = idx >> 2, e = idx & 3;
            int cc = (e == 3) ? 127 : e;
            stg_cs_f(&out_perfect[(size_t)(rowBase + rr) * NROWS + colBase + cc],
                     (labR[rr] == labC[cc]) ? 1.f : -1.f);
        }
    }
    if (!isDiag) {
        int4 lr4 = *(const int4*)&labR[4 * lane];
        int lrm1 = __shfl_up_sync(0xffffffffu, lr4.w, 1);
        #pragma unroll
        for (int i = 0; i < 16; i++) {
            int rr = wid + i * 8;
            int lc_ = labC[rr];
            if (lane > 0) {
                float4 o;
                o.x = (lrm1  == lc_) ? 1.f : -1.f;
                o.y = (lr4.x == lc_) ? 1.f : -1.f;
                o.z = (lr4.y == lc_) ? 1.f : -1.f;
                o.w = (lr4.z == lc_) ? 1.f : -1.f;
                stg_cs_f4(&out_perfect[(size_t)(colBase + rr) * NROWS + rowBase + 4 * lane - 1], o);
            }
        }
        #pragma unroll
        for (int i = 0; i < 2; i++) {
            int idx = tid + i * 256;
            int rr = idx >> 2, e = idx & 3;
            int cc = (e == 3) ? 127 : e;
            stg_cs_f(&out_perfect[(size_t)(colBase + rr) * NROWS + rowBase + cc],
                     (labC[rr] == labR[cc]) ? 1.f : -1.f);
        }
    }
}

// ---------------------------------------------------------------------------
// K2: reduce partials -> per-row value; block-reduce loss partials.
// ---------------------------------------------------------------------------
__global__ void rowfinal_kernel() {
    const int tid = threadIdx.x;
    int i = blockIdx.x * 256 + tid;
    float D = 0.f, P = 0.f, C = 0.f;
    #pragma unroll 4
    for (int b = 0; b < NCOLB; b++) {
        D += g_denp[(size_t)b * NROWS + i];
        P += g_posp[(size_t)b * NROWS + i];
        C += g_cntp[(size_t)b * NROWS + i];
    }
    float rv = -(P - C * logf(D)) / (C + 1e-6f);
    g_rowval[i] = rv;

    __shared__ float rd[8];
    float s = rv;
    #pragma unroll
    for (int o = 16; o > 0; o >>= 1) s += __shfl_xor_sync(0xffffffffu, s, o);
    if ((tid & 31) == 0) rd[tid >> 5] = s;
    __syncthreads();
    if (tid == 0) {
        float tot = 0.f;
        #pragma unroll
        for (int w = 0; w < 8; w++) tot += rd[w];
        g_losspart[blockIdx.x] = tot;
    }
}

// ---------------------------------------------------------------------------
// K3: loss = sum(g_losspart) / NROWS  (one warp)
// ---------------------------------------------------------------------------
__global__ void loss_kernel(float* __restrict__ out) {
    const int tid = threadIdx.x;                 // 32
    float s = g_losspart[tid];
    #pragma unroll
    for (int o = 16; o > 0; o >>= 1) s += __shfl_xor_sync(0xffffffffu, s, o);
    if (tid == 0) out[0] = s / (float)NROWS;
}

// ---------------------------------------------------------------------------
// Launch: out = [loss(1) | logits(8192^2) | perfect_logit(8192^2)]
// ---------------------------------------------------------------------------
extern "C" void kernel_launch(void* const* d_in, const int* in_sizes, int n_in,
                              void* d_out, int out_size) {
    const float* features = (const float*)d_in[0];
    const int*   labels   = (const int*)d_in[1];
    float* out         = (float*)d_out;
    float* out_logits  = out + 1;
    float* out_perfect = out + 1 + (size_t)NROWS * NROWS;

    normalize_kernel<<<NROWS / 16, 256>>>(features);
    gemm_tc<<<NTILES, 256>>>(labels, out_logits, out_perfect);   // 2080 CTAs
    rowfinal_kernel<<<NROWS / 256, 256>>>();                     // 32 blocks
    loss_kernel<<<1, 32>>>(out);
}